// round 13
// baseline (speedup 1.0000x reference)
#include <cuda_runtime.h>
#include <cuda_bf16.h>
#include <cuda_fp16.h>
#include <math.h>
#include <stdint.h>

#define N_NODES 50000
#define N_EDGES 800000
#define HID     128
#define N_GRAPHS 64
#define N_HALF  25000

// ---------------- scratch (allocation-free: __device__ globals) ----------------
__device__ __half d_S0[N_NODES * HID];    // GEMM output ping
__device__ __half d_S1[N_NODES * HID];    // GEMM output pong
__device__ __half d_G1[N_NODES * HID];
__device__ __half d_G2[N_NODES * HID];
__device__ __half d_G3[N_NODES * HID];
__device__ float d_T [N_NODES];
__device__ float d_SC[N_NODES];
__device__ float d_POOL[N_GRAPHS * 6 * HID];
// CSR scratch
__device__ int   d_CNT[N_NODES];
__device__ int   d_ROWPTR[N_NODES + 1];
__device__ int   d_CUR[N_NODES];
__device__ int2  d_EDGE[N_EDGES];         // {src, weight bits}
// pooling partials
__device__ float d_PPS[N_GRAPHS * 4 * 384];
__device__ float d_PPM[N_GRAPHS * 4 * 384];
__device__ int   d_GCNT[N_GRAPHS];
// W converted: transposed [n][kpair] packed fp16x2, hi/lo, 3 layers
__device__ uint32_t d_WH[3][128 * 64];
__device__ uint32_t d_WL[3][128 * 64];

// ---- fp16 hi/lo split + pack ----
__device__ __forceinline__ uint32_t packh2(__half a, __half b)
{
    __half2 h = __halves2half2(a, b);
    return *(uint32_t*)&h;
}
__device__ __forceinline__ void cvt_hilo16(float x, float y, uint32_t& hi, uint32_t& lo)
{
    __half h0 = __float2half_rn(x);
    __half h1 = __float2half_rn(y);
    float rx = x - __half2float(h0);
    float ry = y - __half2float(h1);
    hi = packh2(h0, h1);
    lo = packh2(__float2half_rn(rx), __float2half_rn(ry));
}

#define MMA_F16(c0,c1,c2,c3, a0,a1,a2,a3, b0,b1) \
    asm("mma.sync.aligned.m16n8k16.row.col.f32.f16.f16.f32 " \
        "{%0,%1,%2,%3}, {%4,%5,%6,%7}, {%8,%9}, {%0,%1,%2,%3};" \
        : "+f"(c0), "+f"(c1), "+f"(c2), "+f"(c3) \
        : "r"(a0), "r"(a1), "r"(a2), "r"(a3), "r"(b0), "r"(b1))

// ================= W prep =================
__global__ __launch_bounds__(256) void wprep3(const float* __restrict__ W1,
                                              const float* __restrict__ W2,
                                              const float* __restrict__ W3,
                                              uint32_t* __restrict__ hi,
                                              uint32_t* __restrict__ lo)
{
    int idx = blockIdx.x * blockDim.x + threadIdx.x;
    if (idx >= 3 * 128 * 64) return;
    int layer = idx >> 13;
    int r     = idx & 8191;
    const float* W = (layer == 0) ? W1 : (layer == 1) ? W2 : W3;
    int n = r >> 6, p = r & 63;
    float w0 = W[(2 * p) * 128 + n];
    float w1 = W[(2 * p + 1) * 128 + n];
    uint32_t h, l;
    cvt_hilo16(w0, w1, h, l);
    hi[idx] = h;
    lo[idx] = l;
}

// ================= CSR build =================
__global__ __launch_bounds__(256) void csr_count(const int* __restrict__ dst, int* __restrict__ cnt)
{
    int e = blockIdx.x * blockDim.x + threadIdx.x;
    if (e < N_EDGES) atomicAdd(&cnt[dst[e]], 1);
}

__global__ __launch_bounds__(1024) void csr_scan(const int* __restrict__ cnt,
                                                 int* __restrict__ rowptr,
                                                 int* __restrict__ cur)
{
    __shared__ int warpsum[32];
    __shared__ int carry;
    int t = threadIdx.x, lane = t & 31, w = t >> 5;
    if (t == 0) carry = 0;
    __syncthreads();
    for (int base = 0; base < N_NODES; base += 1024) {
        int i = base + t;
        int v = (i < N_NODES) ? cnt[i] : 0;
        int x = v;
#pragma unroll
        for (int off = 1; off < 32; off <<= 1) {
            int y = __shfl_up_sync(0xFFFFFFFFu, x, off);
            if (lane >= off) x += y;
        }
        if (lane == 31) warpsum[w] = x;
        __syncthreads();
        if (w == 0) {
            int s = warpsum[lane];
#pragma unroll
            for (int off = 1; off < 32; off <<= 1) {
                int y = __shfl_up_sync(0xFFFFFFFFu, s, off);
                if (lane >= off) s += y;
            }
            warpsum[lane] = s;
        }
        __syncthreads();
        int incl = x + (w > 0 ? warpsum[w - 1] : 0);
        if (i < N_NODES) {
            int ex = carry + incl - v;
            rowptr[i] = ex;
            cur[i]    = ex;
        }
        __syncthreads();
        if (t == 1023) carry += warpsum[31];
        __syncthreads();
    }
    if (t == 0) rowptr[N_NODES] = carry;
}

__global__ __launch_bounds__(256) void csr_fill(const int* __restrict__ src,
                                                const int* __restrict__ dst,
                                                const float* __restrict__ ew,
                                                int* __restrict__ cur,
                                                int2* __restrict__ edge)
{
    int e = blockIdx.x * blockDim.x + threadIdx.x;
    if (e >= N_EDGES) return;
    int d = dst[e];
    int p = atomicAdd(&cur[d], 1);
    edge[p] = make_int2(src[e], __float_as_int(ew[e]));
}

// ===== GEMM via fp16 tensor cores (row-range local: caller offsets pointers) =====
#define ASTR 36
#define SM_CH (128 * ASTR)
#define GEMM_SMEM (4 * SM_CH * 4)

template <typename TIn, bool SPLIT_A>
__global__ __launch_bounds__(256, 2) void gemm_f16(const TIn* __restrict__ X,
                                                   const uint32_t* __restrict__ Wthi,
                                                   const uint32_t* __restrict__ Wtlo,
                                                   __half* __restrict__ out, int nrows)
{
    extern __shared__ uint32_t sm[];
    uint32_t* Ahi = sm;
    uint32_t* Alo = sm + SM_CH;
    uint32_t* Bhi = sm + 2 * SM_CH;
    uint32_t* Blo = sm + 3 * SM_CH;

    const int tid  = threadIdx.x;
    const int row0 = blockIdx.x * 128;
    const int warp = tid >> 5, lane = tid & 31;
    const int g    = lane >> 2, tig = lane & 3;
    const int wm   = warp >> 1, wn = warp & 1;

    float c[2][8][4];
#pragma unroll
    for (int mi = 0; mi < 2; ++mi)
#pragma unroll
        for (int ni = 0; ni < 8; ++ni)
#pragma unroll
            for (int q = 0; q < 4; ++q) c[mi][ni][q] = 0.f;

    for (int chunk = 0; chunk < 2; ++chunk) {
        int kp0 = chunk * 32;
        __syncthreads();
#pragma unroll
        for (int i = 0; i < 16; ++i) {
            int idx = i * 256 + tid;
            int r = idx >> 5, p = idx & 31;
            int gr = row0 + r;
            if (SPLIT_A) {
                float2 v = (gr < nrows)
                    ? *(const float2*)((const float*)X + (size_t)gr * 128 + (kp0 + p) * 2)
                    : make_float2(0.f, 0.f);
                uint32_t h, l;
                cvt_hilo16(v.x, v.y, h, l);
                Ahi[r * ASTR + p] = h;
                Alo[r * ASTR + p] = l;
            } else {
                uint32_t h = (gr < nrows)
                    ? *(const uint32_t*)((const __half*)X + (size_t)gr * 128 + (kp0 + p) * 2)
                    : 0u;
                Ahi[r * ASTR + p] = h;
            }
            Bhi[r * ASTR + p] = Wthi[r * 64 + kp0 + p];
            Blo[r * ASTR + p] = Wtlo[r * 64 + kp0 + p];
        }
        __syncthreads();

        const int aB0 = (wm * 32 + g) * ASTR + tig;
        const int bB0 = (wn * 64 + g) * ASTR + tig;
#pragma unroll
        for (int ks = 0; ks < 4; ++ks) {
            int pb = ks * 8;
            uint32_t ah[2][4], al[2][4];
#pragma unroll
            for (int mi = 0; mi < 2; ++mi) {
                int ab = aB0 + mi * 16 * ASTR + pb;
                ah[mi][0] = Ahi[ab];
                ah[mi][1] = Ahi[ab + 8 * ASTR];
                ah[mi][2] = Ahi[ab + 4];
                ah[mi][3] = Ahi[ab + 8 * ASTR + 4];
                if (SPLIT_A) {
                    al[mi][0] = Alo[ab];
                    al[mi][1] = Alo[ab + 8 * ASTR];
                    al[mi][2] = Alo[ab + 4];
                    al[mi][3] = Alo[ab + 8 * ASTR + 4];
                }
            }
#pragma unroll
            for (int ni = 0; ni < 8; ++ni) {
                int bb = bB0 + ni * 8 * ASTR + pb;
                uint32_t bh0 = Bhi[bb];
                uint32_t bh1 = Bhi[bb + 4];
                uint32_t bl0 = Blo[bb];
                uint32_t bl1 = Blo[bb + 4];
#pragma unroll
                for (int mi = 0; mi < 2; ++mi) {
                    MMA_F16(c[mi][ni][0], c[mi][ni][1], c[mi][ni][2], c[mi][ni][3],
                            ah[mi][0], ah[mi][1], ah[mi][2], ah[mi][3], bh0, bh1);
                    MMA_F16(c[mi][ni][0], c[mi][ni][1], c[mi][ni][2], c[mi][ni][3],
                            ah[mi][0], ah[mi][1], ah[mi][2], ah[mi][3], bl0, bl1);
                    if (SPLIT_A)
                        MMA_F16(c[mi][ni][0], c[mi][ni][1], c[mi][ni][2], c[mi][ni][3],
                                al[mi][0], al[mi][1], al[mi][2], al[mi][3], bh0, bh1);
                }
            }
        }
    }

#pragma unroll
    for (int mi = 0; mi < 2; ++mi) {
        int r = row0 + wm * 32 + mi * 16 + g;
#pragma unroll
        for (int ni = 0; ni < 8; ++ni) {
            int cn = wn * 64 + ni * 8 + 2 * tig;
            if (r < nrows)
                *(__half2*)&out[(size_t)r * 128 + cn] = __floats2half2_rn(c[mi][ni][0], c[mi][ni][1]);
            if (r + 8 < nrows)
                *(__half2*)&out[(size_t)(r + 8) * 128 + cn] = __floats2half2_rn(c[mi][ni][2], c[mi][ni][3]);
        }
    }
}

// ==== CSR gather (fp16 source, packed edges, node range) ====
__device__ __forceinline__ void acc_row(float4& acc, const __half* __restrict__ S,
                                        int s, int lane, float w)
{
    uint2 u = ((const uint2*)(S + (size_t)s * 128))[lane];
    __half2 p0 = *(__half2*)&u.x;
    __half2 p1 = *(__half2*)&u.y;
    float2 f0 = __half22float2(p0);
    float2 f1 = __half22float2(p1);
    acc.x = fmaf(w, f0.x, acc.x);
    acc.y = fmaf(w, f0.y, acc.y);
    acc.z = fmaf(w, f1.x, acc.z);
    acc.w = fmaf(w, f1.y, acc.w);
}

__global__ __launch_bounds__(256) void gather_relu(const int* __restrict__ rowptr,
                                                   const int2* __restrict__ edge,
                                                   const __half* __restrict__ S,
                                                   const float* __restrict__ b,
                                                   const float* __restrict__ wa_seg,
                                                   __half* __restrict__ out,
                                                   float* __restrict__ T,
                                                   int accum, int node_base, int node_cnt)
{
    int gt   = blockIdx.x * blockDim.x + threadIdx.x;
    int nrel = gt >> 5;
    int lane = gt & 31;
    if (nrel >= node_cnt) return;
    int node = node_base + nrel;

    int e0 = rowptr[node], e1 = rowptr[node + 1];
    float4 acc = make_float4(0.f, 0.f, 0.f, 0.f);

    int e = e0;
    for (; e + 3 < e1; e += 4) {
        int2 d0 = __ldg(edge + e);
        int2 d1 = __ldg(edge + e + 1);
        int2 d2 = __ldg(edge + e + 2);
        int2 d3 = __ldg(edge + e + 3);
        acc_row(acc, S, d0.x, lane, __int_as_float(d0.y));
        acc_row(acc, S, d1.x, lane, __int_as_float(d1.y));
        acc_row(acc, S, d2.x, lane, __int_as_float(d2.y));
        acc_row(acc, S, d3.x, lane, __int_as_float(d3.y));
    }
    for (; e < e1; ++e) {
        int2 d0 = __ldg(edge + e);
        acc_row(acc, S, d0.x, lane, __int_as_float(d0.y));
    }

    float4 bb = ((const float4*)b)[lane];
    acc.x = fmaxf(acc.x + bb.x, 0.f);
    acc.y = fmaxf(acc.y + bb.y, 0.f);
    acc.z = fmaxf(acc.z + bb.z, 0.f);
    acc.w = fmaxf(acc.w + bb.w, 0.f);

    uint2 st;
    *(__half2*)&st.x = __floats2half2_rn(acc.x, acc.y);
    *(__half2*)&st.y = __floats2half2_rn(acc.z, acc.w);
    ((uint2*)(out + (size_t)node * 128))[lane] = st;

    float4 ww = ((const float4*)wa_seg)[lane];
    float s = acc.x * ww.x + acc.y * ww.y + acc.z * ww.z + acc.w * ww.w;
#pragma unroll
    for (int off = 16; off; off >>= 1) s += __shfl_xor_sync(0xFFFFFFFFu, s, off);
    if (lane == 0) {
        if (accum) T[node] += s;
        else       T[node]  = s;
    }
}

// ---------- sc[node] = tanh( sum_e w_e * t[src_e] + ba ) ----------
__global__ __launch_bounds__(256) void gather_score(const int* __restrict__ rowptr,
                                                    const int2* __restrict__ edge,
                                                    const float* __restrict__ t,
                                                    const float* __restrict__ ba,
                                                    float* __restrict__ sc)
{
    int gt   = blockIdx.x * blockDim.x + threadIdx.x;
    int node = gt >> 5;
    int lane = gt & 31;
    if (node >= N_NODES) return;

    int e0 = rowptr[node], e1 = rowptr[node + 1];
    float s = 0.f;
    for (int e = e0 + lane; e < e1; e += 32) {
        int2 d = __ldg(edge + e);
        s = fmaf(__int_as_float(d.y), __ldg(t + d.x), s);
    }
#pragma unroll
    for (int off = 16; off; off >>= 1) s += __shfl_xor_sync(0xFFFFFFFFu, s, off);
    if (lane == 0) sc[node] = tanhf(s + ba[0]);
}

// ---------------- per-graph pooling ----------------
__device__ __forceinline__ int lowerb(const int* a, int n, int v)
{
    int lo = 0, hi = n;
    while (lo < hi) { int m = (lo + hi) >> 1; if (a[m] < v) lo = m + 1; else hi = m; }
    return lo;
}

__global__ __launch_bounds__(384) void pool_part(const __half* __restrict__ g1,
                                                 const __half* __restrict__ g2,
                                                 const __half* __restrict__ g3,
                                                 const float* __restrict__ score,
                                                 const int* __restrict__ gi,
                                                 float* __restrict__ pps,
                                                 float* __restrict__ ppm,
                                                 int* __restrict__ gcnt)
{
    int b = blockIdx.x;
    int g = b >> 2, part = b & 3;
    int c = threadIdx.x;
    __shared__ int sS, sE;
    if (c == 0) sS = lowerb(gi, N_NODES, g);
    if (c == 1) sE = lowerb(gi, N_NODES, g + 1);
    __syncthreads();
    int start = sS, end = sE, len = end - start;
    int n0 = start + (len * part) / 4;
    int n1 = start + (len * (part + 1)) / 4;

    const __half* base = (c < 128) ? g1 : (c < 256) ? g2 : g3;
    int cc = c & 127;

    float sum = 0.f, mx = -INFINITY;
    for (int n = n0; n < n1; ++n) {
        float v = __half2float(base[(size_t)n * 128 + cc]) * score[n];
        sum += v;
        mx = fmaxf(mx, v);
    }
    pps[b * 384 + c] = sum;
    ppm[b * 384 + c] = mx;
    if (part == 0 && c == 0) gcnt[g] = len;
}

__global__ __launch_bounds__(384) void pool_comb(const float* __restrict__ pps,
                                                 const float* __restrict__ ppm,
                                                 const int* __restrict__ gcnt,
                                                 float* __restrict__ pooled)
{
    int g = blockIdx.x, c = threadIdx.x;
    float sum = 0.f, mx = -INFINITY;
#pragma unroll
    for (int p = 0; p < 4; ++p) {
        sum += pps[(g * 4 + p) * 384 + c];
        mx = fmaxf(mx, ppm[(g * 4 + p) * 384 + c]);
    }
    float cnt = (float)gcnt[g];
    pooled[g * 768 + c]       = sum / fmaxf(cnt, 1.f);
    pooled[g * 768 + 384 + c] = mx;
}

// ---------------- out = relu(pooled @ Wf + bf) ----------------
__global__ __launch_bounds__(128) void final_k(const float* __restrict__ pooled,
                                               const float* __restrict__ Wf,
                                               const float* __restrict__ bf,
                                               float* __restrict__ out)
{
    int g = blockIdx.x, c = threadIdx.x;
    __shared__ float pr[768];
    for (int i = c; i < 768; i += 128) pr[i] = pooled[g * 768 + i];
    __syncthreads();
    float acc = bf[c];
#pragma unroll 8
    for (int k = 0; k < 768; ++k) acc = fmaf(pr[k], Wf[k * 128 + c], acc);
    out[g * 128 + c] = fmaxf(acc, 0.f);
}

// ---------------- launch ----------------
extern "C" void kernel_launch(void* const* d_in, const int* in_sizes, int n_in,
                              void* d_out, int out_size)
{
    const int*   ei  = (const int*)d_in[0];
    const float* ew  = (const float*)d_in[1];
    const float* X   = (const float*)d_in[2];
    const int*   gi  = (const int*)d_in[3];
    const float* W1  = (const float*)d_in[4];
    const float* b1  = (const float*)d_in[5];
    const float* W2  = (const float*)d_in[6];
    const float* b2  = (const float*)d_in[7];
    const float* W3  = (const float*)d_in[8];
    const float* b3  = (const float*)d_in[9];
    const float* wa  = (const float*)d_in[10];
    const float* ba  = (const float*)d_in[11];
    const float* Wf  = (const float*)d_in[12];
    const float* bf  = (const float*)d_in[13];
    float* out = (float*)d_out;

    const int* src = ei;
    const int* dst = ei + N_EDGES;

    static int inited = 0;
    static cudaStream_t s2;
    static cudaEvent_t evFork, evCSR, evA, evB, evC, evD;
    if (!inited) {
        cudaFuncSetAttribute(gemm_f16<float, true>,   cudaFuncAttributeMaxDynamicSharedMemorySize, GEMM_SMEM);
        cudaFuncSetAttribute(gemm_f16<__half, false>, cudaFuncAttributeMaxDynamicSharedMemorySize, GEMM_SMEM);
        cudaStreamCreateWithFlags(&s2, cudaStreamNonBlocking);
        cudaEventCreateWithFlags(&evFork, cudaEventDisableTiming);
        cudaEventCreateWithFlags(&evCSR,  cudaEventDisableTiming);
        cudaEventCreateWithFlags(&evA, cudaEventDisableTiming);
        cudaEventCreateWithFlags(&evB, cudaEventDisableTiming);
        cudaEventCreateWithFlags(&evC, cudaEventDisableTiming);
        cudaEventCreateWithFlags(&evD, cudaEventDisableTiming);
        inited = 1;
    }

    void *pS0, *pS1, *pG1, *pG2, *pG3, *pT, *pSC, *pPOOL;
    void *pCNT, *pRP, *pCUR, *pEDGE, *pPPS, *pPPM, *pGC, *pWH, *pWL;
    cudaGetSymbolAddress(&pS0,  d_S0);
    cudaGetSymbolAddress(&pS1,  d_S1);
    cudaGetSymbolAddress(&pG1,  d_G1);
    cudaGetSymbolAddress(&pG2,  d_G2);
    cudaGetSymbolAddress(&pG3,  d_G3);
    cudaGetSymbolAddress(&pT,   d_T);
    cudaGetSymbolAddress(&pSC,  d_SC);
    cudaGetSymbolAddress(&pPOOL, d_POOL);
    cudaGetSymbolAddress(&pCNT, d_CNT);
    cudaGetSymbolAddress(&pRP,  d_ROWPTR);
    cudaGetSymbolAddress(&pCUR, d_CUR);
    cudaGetSymbolAddress(&pEDGE, d_EDGE);
    cudaGetSymbolAddress(&pPPS, d_PPS);
    cudaGetSymbolAddress(&pPPM, d_PPM);
    cudaGetSymbolAddress(&pGC,  d_GCNT);
    cudaGetSymbolAddress(&pWH,  d_WH);
    cudaGetSymbolAddress(&pWL,  d_WL);

    __half* S0 = (__half*)pS0;
    __half* S1 = (__half*)pS1;
    __half* G1 = (__half*)pG1;
    __half* G2 = (__half*)pG2;
    __half* G3 = (__half*)pG3;
    float* T   = (float*)pT;
    float* SC  = (float*)pSC;
    float* PO  = (float*)pPOOL;
    int*   CNT = (int*)pCNT;
    int*   RP  = (int*)pRP;
    int*   CUR = (int*)pCUR;
    int2*  EDGE = (int2*)pEDGE;
    float* PPS = (float*)pPPS;
    float* PPM = (float*)pPPM;
    int*   GC  = (int*)pGC;
    uint32_t* WH = (uint32_t*)pWH;
    uint32_t* WL = (uint32_t*)pWL;

    const int gemm_grid  = (N_NODES + 127) / 128;        // full
    const int gemm_gridH = (N_HALF + 127) / 128;         // half
    const int edge_grid  = (N_EDGES + 255) / 256;
    const int warp_grid  = (N_NODES * 32 + 255) / 256;   // full gather
    const int warp_gridH = (N_HALF * 32 + 255) / 256;    // half gather

    // ---- fork: CSR build on s2, concurrent with wprep + gemm1 ----
    cudaEventRecord(evFork, 0);
    cudaStreamWaitEvent(s2, evFork, 0);

    cudaMemsetAsync(CNT, 0, N_NODES * sizeof(int), s2);
    csr_count<<<edge_grid, 256, 0, s2>>>(dst, CNT);
    csr_scan<<<1, 1024, 0, s2>>>(CNT, RP, CUR);
    csr_fill<<<edge_grid, 256, 0, s2>>>(src, dst, ew, CUR, EDGE);
    cudaEventRecord(evCSR, s2);

    // ---- main: wprep + gemm1 (full, -> S0) ----
    wprep3<<<96, 256>>>(W1, W2, W3, WH, WL);
    gemm_f16<float, true><<<gemm_grid, 256, GEMM_SMEM>>>(X, WH, WL, S0, N_NODES);

    cudaStreamWaitEvent(0, evCSR, 0);

    // ---- layer 1 gather (S0 -> G1), half A then half B; gemm2_A overlaps gather1_B ----
    gather_relu<<<warp_gridH, 256>>>(RP, EDGE, S0, b1, wa, G1, T, 0, 0, N_HALF);
    cudaEventRecord(evA, 0);
    cudaStreamWaitEvent(s2, evA, 0);
    gemm_f16<__half, false><<<gemm_gridH, 256, GEMM_SMEM, s2>>>(G1, WH + 8192, WL + 8192, S1, N_HALF);
    cudaEventRecord(evB, s2);

    gather_relu<<<warp_gridH, 256>>>(RP, EDGE, S0, b1, wa, G1, T, 0, N_HALF, N_NODES - N_HALF);
    gemm_f16<__half, false><<<gemm_gridH, 256, GEMM_SMEM>>>(G1 + (size_t)N_HALF * 128,
                                                            WH + 8192, WL + 8192,
                                                            S1 + (size_t)N_HALF * 128,
                                                            N_NODES - N_HALF);
    cudaStreamWaitEvent(0, evB, 0);

    // ---- layer 2 gather (S1 -> G2); gemm3_A overlaps gather2_B ----
    gather_relu<<<warp_gridH, 256>>>(RP, EDGE, S1, b2, wa + 128, G2, T, 1, 0, N_HALF);
    cudaEventRecord(evC, 0);
    cudaStreamWaitEvent(s2, evC, 0);
    gemm_f16<__half, false><<<gemm_gridH, 256, GEMM_SMEM, s2>>>(G2, WH + 16384, WL + 16384, S0, N_HALF);
    cudaEventRecord(evD, s2);

    gather_relu<<<warp_gridH, 256>>>(RP, EDGE, S1, b2, wa + 128, G2, T, 1, N_HALF, N_NODES - N_HALF);
    gemm_f16<__half, false><<<gemm_gridH, 256, GEMM_SMEM>>>(G2 + (size_t)N_HALF * 128,
                                                            WH + 16384, WL + 16384,
                                                            S0 + (size_t)N_HALF * 128,
                                                            N_NODES - N_HALF);
    cudaStreamWaitEvent(0, evD, 0);

    // ---- layer 3 gather (S0 -> G3, full) ----
    gather_relu<<<warp_grid, 256>>>(RP, EDGE, S0, b3, wa + 256, G3, T, 1, 0, N_NODES);

    // ---- attention score ----
    gather_score<<<warp_grid, 256>>>(RP, EDGE, T, ba, SC);

    // ---- pooling + final FC ----
    pool_part<<<N_GRAPHS * 4, 384>>>(G1, G2, G3, SC, gi, PPS, PPM, GC);
    pool_comb<<<N_GRAPHS, 384>>>(PPS, PPM, GC, PO);
    final_k<<<N_GRAPHS, 128>>>(PO, Wf, bf, out);

    (void)in_sizes; (void)n_in; (void)out_size;
}

// round 14
// speedup vs baseline: 1.0350x; 1.0350x over previous
#include <cuda_runtime.h>
#include <cuda_bf16.h>
#include <cuda_fp16.h>
#include <math.h>
#include <stdint.h>

#define N_NODES 50000
#define N_EDGES 800000
#define HID     128
#define N_GRAPHS 64

// ---------------- scratch (allocation-free: __device__ globals) ----------------
__device__ __half d_S16[N_NODES * HID];
__device__ __half d_G1[N_NODES * HID];
__device__ __half d_G2[N_NODES * HID];
__device__ __half d_G3[N_NODES * HID];
__device__ float d_T [N_NODES];
__device__ float d_SC[N_NODES];
// CSR scratch
__device__ int   d_CNT[N_NODES];
__device__ int   d_ROWPTR[N_NODES + 1];
__device__ int   d_CUR[N_NODES];
__device__ int2  d_EDGE[N_EDGES];
// pooling partials
__device__ float d_PPS[N_GRAPHS * 4 * 384];
__device__ float d_PPM[N_GRAPHS * 4 * 384];
__device__ int   d_GCNT[N_GRAPHS];
// W converted: transposed [n][kpair] packed fp16x2, hi/lo, 3 layers
__device__ uint32_t d_WH[3][128 * 64];
__device__ uint32_t d_WL[3][128 * 64];

// ---- fp16 hi/lo split + pack ----
__device__ __forceinline__ uint32_t packh2(__half a, __half b)
{
    __half2 h = __halves2half2(a, b);
    return *(uint32_t*)&h;
}
__device__ __forceinline__ void cvt_hilo16(float x, float y, uint32_t& hi, uint32_t& lo)
{
    __half h0 = __float2half_rn(x);
    __half h1 = __float2half_rn(y);
    float rx = x - __half2float(h0);
    float ry = y - __half2float(h1);
    hi = packh2(h0, h1);
    lo = packh2(__float2half_rn(rx), __float2half_rn(ry));
}

#define MMA_F16(c0,c1,c2,c3, a0,a1,a2,a3, b0,b1) \
    asm("mma.sync.aligned.m16n8k16.row.col.f32.f16.f16.f32 " \
        "{%0,%1,%2,%3}, {%4,%5,%6,%7}, {%8,%9}, {%0,%1,%2,%3};" \
        : "+f"(c0), "+f"(c1), "+f"(c2), "+f"(c3) \
        : "r"(a0), "r"(a1), "r"(a2), "r"(a3), "r"(b0), "r"(b1))

// ================= W prep (single layer) =================
__global__ __launch_bounds__(256) void wprep(const float* __restrict__ W,
                                             uint32_t* __restrict__ hi,
                                             uint32_t* __restrict__ lo)
{
    int idx = blockIdx.x * blockDim.x + threadIdx.x;   // 0..8191
    if (idx >= 128 * 64) return;
    int n = idx >> 6, p = idx & 63;
    float w0 = W[(2 * p) * 128 + n];
    float w1 = W[(2 * p + 1) * 128 + n];
    uint32_t h, l;
    cvt_hilo16(w0, w1, h, l);
    hi[n * 64 + p] = h;
    lo[n * 64 + p] = l;
}

// ================= CSR build =================
__global__ __launch_bounds__(256) void csr_count(const int* __restrict__ dst, int* __restrict__ cnt)
{
    int e = blockIdx.x * blockDim.x + threadIdx.x;
    if (e < N_EDGES) atomicAdd(&cnt[dst[e]], 1);
}

__global__ __launch_bounds__(1024) void csr_scan(const int* __restrict__ cnt,
                                                 int* __restrict__ rowptr,
                                                 int* __restrict__ cur)
{
    __shared__ int warpsum[32];
    __shared__ int carry;
    int t = threadIdx.x, lane = t & 31, w = t >> 5;
    if (t == 0) carry = 0;
    __syncthreads();
    for (int base = 0; base < N_NODES; base += 1024) {
        int i = base + t;
        int v = (i < N_NODES) ? cnt[i] : 0;
        int x = v;
#pragma unroll
        for (int off = 1; off < 32; off <<= 1) {
            int y = __shfl_up_sync(0xFFFFFFFFu, x, off);
            if (lane >= off) x += y;
        }
        if (lane == 31) warpsum[w] = x;
        __syncthreads();
        if (w == 0) {
            int s = warpsum[lane];
#pragma unroll
            for (int off = 1; off < 32; off <<= 1) {
                int y = __shfl_up_sync(0xFFFFFFFFu, s, off);
                if (lane >= off) s += y;
            }
            warpsum[lane] = s;
        }
        __syncthreads();
        int incl = x + (w > 0 ? warpsum[w - 1] : 0);
        if (i < N_NODES) {
            int ex = carry + incl - v;
            rowptr[i] = ex;
            cur[i]    = ex;
        }
        __syncthreads();
        if (t == 1023) carry += warpsum[31];
        __syncthreads();
    }
    if (t == 0) rowptr[N_NODES] = carry;
}

__global__ __launch_bounds__(256) void csr_fill(const int* __restrict__ src,
                                                const int* __restrict__ dst,
                                                const float* __restrict__ ew,
                                                int* __restrict__ cur,
                                                int2* __restrict__ edge)
{
    int e = blockIdx.x * blockDim.x + threadIdx.x;
    if (e >= N_EDGES) return;
    int d = dst[e];
    int p = atomicAdd(&cur[d], 1);
    edge[p] = make_int2(src[e], __float_as_int(ew[e]));
}

// ===== GEMM via fp16 tensor cores =====
#define ASTR 36
#define SM_CH (128 * ASTR)
#define GEMM_SMEM (4 * SM_CH * 4)

template <typename TIn, bool SPLIT_A>
__global__ __launch_bounds__(256, 2) void gemm_f16(const TIn* __restrict__ X,
                                                   const uint32_t* __restrict__ Wthi,
                                                   const uint32_t* __restrict__ Wtlo,
                                                   __half* __restrict__ out, int nrows)
{
    extern __shared__ uint32_t sm[];
    uint32_t* Ahi = sm;
    uint32_t* Alo = sm + SM_CH;
    uint32_t* Bhi = sm + 2 * SM_CH;
    uint32_t* Blo = sm + 3 * SM_CH;

    const int tid  = threadIdx.x;
    const int row0 = blockIdx.x * 128;
    const int warp = tid >> 5, lane = tid & 31;
    const int g    = lane >> 2, tig = lane & 3;
    const int wm   = warp >> 1, wn = warp & 1;

    float c[2][8][4];
#pragma unroll
    for (int mi = 0; mi < 2; ++mi)
#pragma unroll
        for (int ni = 0; ni < 8; ++ni)
#pragma unroll
            for (int q = 0; q < 4; ++q) c[mi][ni][q] = 0.f;

    for (int chunk = 0; chunk < 2; ++chunk) {
        int kp0 = chunk * 32;
        __syncthreads();
#pragma unroll
        for (int i = 0; i < 16; ++i) {
            int idx = i * 256 + tid;
            int r = idx >> 5, p = idx & 31;
            int gr = row0 + r;
            if (SPLIT_A) {
                float2 v = (gr < nrows)
                    ? *(const float2*)((const float*)X + (size_t)gr * 128 + (kp0 + p) * 2)
                    : make_float2(0.f, 0.f);
                uint32_t h, l;
                cvt_hilo16(v.x, v.y, h, l);
                Ahi[r * ASTR + p] = h;
                Alo[r * ASTR + p] = l;
            } else {
                uint32_t h = (gr < nrows)
                    ? *(const uint32_t*)((const __half*)X + (size_t)gr * 128 + (kp0 + p) * 2)
                    : 0u;
                Ahi[r * ASTR + p] = h;
            }
            Bhi[r * ASTR + p] = Wthi[r * 64 + kp0 + p];
            Blo[r * ASTR + p] = Wtlo[r * 64 + kp0 + p];
        }
        __syncthreads();

        const int aB0 = (wm * 32 + g) * ASTR + tig;
        const int bB0 = (wn * 64 + g) * ASTR + tig;
#pragma unroll
        for (int ks = 0; ks < 4; ++ks) {
            int pb = ks * 8;
            uint32_t ah[2][4], al[2][4];
#pragma unroll
            for (int mi = 0; mi < 2; ++mi) {
                int ab = aB0 + mi * 16 * ASTR + pb;
                ah[mi][0] = Ahi[ab];
                ah[mi][1] = Ahi[ab + 8 * ASTR];
                ah[mi][2] = Ahi[ab + 4];
                ah[mi][3] = Ahi[ab + 8 * ASTR + 4];
                if (SPLIT_A) {
                    al[mi][0] = Alo[ab];
                    al[mi][1] = Alo[ab + 8 * ASTR];
                    al[mi][2] = Alo[ab + 4];
                    al[mi][3] = Alo[ab + 8 * ASTR + 4];
                }
            }
#pragma unroll
            for (int ni = 0; ni < 8; ++ni) {
                int bb = bB0 + ni * 8 * ASTR + pb;
                uint32_t bh0 = Bhi[bb];
                uint32_t bh1 = Bhi[bb + 4];
                uint32_t bl0 = Blo[bb];
                uint32_t bl1 = Blo[bb + 4];
#pragma unroll
                for (int mi = 0; mi < 2; ++mi) {
                    MMA_F16(c[mi][ni][0], c[mi][ni][1], c[mi][ni][2], c[mi][ni][3],
                            ah[mi][0], ah[mi][1], ah[mi][2], ah[mi][3], bh0, bh1);
                    MMA_F16(c[mi][ni][0], c[mi][ni][1], c[mi][ni][2], c[mi][ni][3],
                            ah[mi][0], ah[mi][1], ah[mi][2], ah[mi][3], bl0, bl1);
                    if (SPLIT_A)
                        MMA_F16(c[mi][ni][0], c[mi][ni][1], c[mi][ni][2], c[mi][ni][3],
                                al[mi][0], al[mi][1], al[mi][2], al[mi][3], bh0, bh1);
                }
            }
        }
    }

#pragma unroll
    for (int mi = 0; mi < 2; ++mi) {
        int r = row0 + wm * 32 + mi * 16 + g;
#pragma unroll
        for (int ni = 0; ni < 8; ++ni) {
            int cn = wn * 64 + ni * 8 + 2 * tig;
            if (r < nrows)
                *(__half2*)&out[(size_t)r * 128 + cn] = __floats2half2_rn(c[mi][ni][0], c[mi][ni][1]);
            if (r + 8 < nrows)
                *(__half2*)&out[(size_t)(r + 8) * 128 + cn] = __floats2half2_rn(c[mi][ni][2], c[mi][ni][3]);
        }
    }
}

// ==== CSR gather (fp16 source, packed edges) + fused attention partial ====
__device__ __forceinline__ void acc_row(float4& acc, const __half* __restrict__ S,
                                        int s, int lane, float w)
{
    uint2 u = ((const uint2*)(S + (size_t)s * 128))[lane];
    __half2 p0 = *(__half2*)&u.x;
    __half2 p1 = *(__half2*)&u.y;
    float2 f0 = __half22float2(p0);
    float2 f1 = __half22float2(p1);
    acc.x = fmaf(w, f0.x, acc.x);
    acc.y = fmaf(w, f0.y, acc.y);
    acc.z = fmaf(w, f1.x, acc.z);
    acc.w = fmaf(w, f1.y, acc.w);
}

__global__ __launch_bounds__(256) void gather_relu(const int* __restrict__ rowptr,
                                                   const int2* __restrict__ edge,
                                                   const __half* __restrict__ S,
                                                   const float* __restrict__ b,
                                                   const float* __restrict__ wa_seg,
                                                   __half* __restrict__ out,
                                                   float* __restrict__ T,
                                                   int accum)
{
    int gt   = blockIdx.x * blockDim.x + threadIdx.x;
    int node = gt >> 5;
    int lane = gt & 31;
    if (node >= N_NODES) return;

    int e0 = rowptr[node], e1 = rowptr[node + 1];
    float4 acc = make_float4(0.f, 0.f, 0.f, 0.f);

    int e = e0;
    for (; e + 7 < e1; e += 8) {
        int2 d0 = __ldg(edge + e);
        int2 d1 = __ldg(edge + e + 1);
        int2 d2 = __ldg(edge + e + 2);
        int2 d3 = __ldg(edge + e + 3);
        int2 d4 = __ldg(edge + e + 4);
        int2 d5 = __ldg(edge + e + 5);
        int2 d6 = __ldg(edge + e + 6);
        int2 d7 = __ldg(edge + e + 7);
        acc_row(acc, S, d0.x, lane, __int_as_float(d0.y));
        acc_row(acc, S, d1.x, lane, __int_as_float(d1.y));
        acc_row(acc, S, d2.x, lane, __int_as_float(d2.y));
        acc_row(acc, S, d3.x, lane, __int_as_float(d3.y));
        acc_row(acc, S, d4.x, lane, __int_as_float(d4.y));
        acc_row(acc, S, d5.x, lane, __int_as_float(d5.y));
        acc_row(acc, S, d6.x, lane, __int_as_float(d6.y));
        acc_row(acc, S, d7.x, lane, __int_as_float(d7.y));
    }
    for (; e + 1 < e1; e += 2) {
        int2 d0 = __ldg(edge + e);
        int2 d1 = __ldg(edge + e + 1);
        acc_row(acc, S, d0.x, lane, __int_as_float(d0.y));
        acc_row(acc, S, d1.x, lane, __int_as_float(d1.y));
    }
    if (e < e1) {
        int2 d0 = __ldg(edge + e);
        acc_row(acc, S, d0.x, lane, __int_as_float(d0.y));
    }

    float4 bb = ((const float4*)b)[lane];
    acc.x = fmaxf(acc.x + bb.x, 0.f);
    acc.y = fmaxf(acc.y + bb.y, 0.f);
    acc.z = fmaxf(acc.z + bb.z, 0.f);
    acc.w = fmaxf(acc.w + bb.w, 0.f);

    uint2 st;
    *(__half2*)&st.x = __floats2half2_rn(acc.x, acc.y);
    *(__half2*)&st.y = __floats2half2_rn(acc.z, acc.w);
    ((uint2*)(out + (size_t)node * 128))[lane] = st;

    float4 ww = ((const float4*)wa_seg)[lane];
    float s = acc.x * ww.x + acc.y * ww.y + acc.z * ww.z + acc.w * ww.w;
#pragma unroll
    for (int off = 16; off; off >>= 1) s += __shfl_xor_sync(0xFFFFFFFFu, s, off);
    if (lane == 0) {
        if (accum) T[node] += s;
        else       T[node]  = s;
    }
}

// ---------- sc[node] = tanh( sum_e w_e * t[src_e] + ba ) ----------
__global__ __launch_bounds__(256) void gather_score(const int* __restrict__ rowptr,
                                                    const int2* __restrict__ edge,
                                                    const float* __restrict__ t,
                                                    const float* __restrict__ ba,
                                                    float* __restrict__ sc)
{
    int gt   = blockIdx.x * blockDim.x + threadIdx.x;
    int node = gt >> 5;
    int lane = gt & 31;
    if (node >= N_NODES) return;

    int e0 = rowptr[node], e1 = rowptr[node + 1];
    float s = 0.f;
    for (int e = e0 + lane; e < e1; e += 32) {
        int2 d = __ldg(edge + e);
        s = fmaf(__int_as_float(d.y), __ldg(t + d.x), s);
    }
#pragma unroll
    for (int off = 16; off; off >>= 1) s += __shfl_xor_sync(0xFFFFFFFFu, s, off);
    if (lane == 0) sc[node] = tanhf(s + ba[0]);
}

// ---------------- per-graph pooling ----------------
__device__ __forceinline__ int lowerb(const int* a, int n, int v)
{
    int lo = 0, hi = n;
    while (lo < hi) { int m = (lo + hi) >> 1; if (a[m] < v) lo = m + 1; else hi = m; }
    return lo;
}

__global__ __launch_bounds__(384) void pool_part(const __half* __restrict__ g1,
                                                 const __half* __restrict__ g2,
                                                 const __half* __restrict__ g3,
                                                 const float* __restrict__ score,
                                                 const int* __restrict__ gi,
                                                 float* __restrict__ pps,
                                                 float* __restrict__ ppm,
                                                 int* __restrict__ gcnt)
{
    int b = blockIdx.x;
    int g = b >> 2, part = b & 3;
    int c = threadIdx.x;
    __shared__ int sS, sE;
    if (c == 0) sS = lowerb(gi, N_NODES, g);
    if (c == 1) sE = lowerb(gi, N_NODES, g + 1);
    __syncthreads();
    int start = sS, end = sE, len = end - start;
    int n0 = start + (len * part) / 4;
    int n1 = start + (len * (part + 1)) / 4;

    const __half* base = (c < 128) ? g1 : (c < 256) ? g2 : g3;
    int cc = c & 127;

    float sum = 0.f, mx = -INFINITY;
    for (int n = n0; n < n1; ++n) {
        float v = __half2float(base[(size_t)n * 128 + cc]) * score[n];
        sum += v;
        mx = fmaxf(mx, v);
    }
    pps[b * 384 + c] = sum;
    ppm[b * 384 + c] = mx;
    if (part == 0 && c == 0) gcnt[g] = len;
}

// ---------------- fused: combine partials -> pooled (smem) -> FC -> out ----------------
__global__ __launch_bounds__(384) void pool_final(const float* __restrict__ pps,
                                                  const float* __restrict__ ppm,
                                                  const int* __restrict__ gcnt,
                                                  const float* __restrict__ Wf,
                                                  const float* __restrict__ bf,
                                                  float* __restrict__ out)
{
    int g = blockIdx.x, c = threadIdx.x;
    __shared__ float pr[768];

    float sum = 0.f, mx = -INFINITY;
#pragma unroll
    for (int p = 0; p < 4; ++p) {
        sum += pps[(g * 4 + p) * 384 + c];
        mx = fmaxf(mx, ppm[(g * 4 + p) * 384 + c]);
    }
    float cnt = (float)gcnt[g];
    pr[c]       = sum / fmaxf(cnt, 1.f);
    pr[384 + c] = mx;
    __syncthreads();

    if (c < 128) {
        float acc = bf[c];
#pragma unroll 8
        for (int k = 0; k < 768; ++k) acc = fmaf(pr[k], Wf[k * 128 + c], acc);
        out[g * 128 + c] = fmaxf(acc, 0.f);
    }
}

// ---------------- launch ----------------
extern "C" void kernel_launch(void* const* d_in, const int* in_sizes, int n_in,
                              void* d_out, int out_size)
{
    const int*   ei  = (const int*)d_in[0];
    const float* ew  = (const float*)d_in[1];
    const float* X   = (const float*)d_in[2];
    const int*   gi  = (const int*)d_in[3];
    const float* W1  = (const float*)d_in[4];
    const float* b1  = (const float*)d_in[5];
    const float* W2  = (const float*)d_in[6];
    const float* b2  = (const float*)d_in[7];
    const float* W3  = (const float*)d_in[8];
    const float* b3  = (const float*)d_in[9];
    const float* wa  = (const float*)d_in[10];
    const float* ba  = (const float*)d_in[11];
    const float* Wf  = (const float*)d_in[12];
    const float* bf  = (const float*)d_in[13];
    float* out = (float*)d_out;

    const int* src = ei;
    const int* dst = ei + N_EDGES;

    static int inited = 0;
    static cudaStream_t s2;
    static cudaEvent_t evFork, evCSR, evW;
    if (!inited) {
        cudaFuncSetAttribute(gemm_f16<float, true>,   cudaFuncAttributeMaxDynamicSharedMemorySize, GEMM_SMEM);
        cudaFuncSetAttribute(gemm_f16<__half, false>, cudaFuncAttributeMaxDynamicSharedMemorySize, GEMM_SMEM);
        cudaStreamCreateWithFlags(&s2, cudaStreamNonBlocking);
        cudaEventCreateWithFlags(&evFork, cudaEventDisableTiming);
        cudaEventCreateWithFlags(&evCSR,  cudaEventDisableTiming);
        cudaEventCreateWithFlags(&evW,    cudaEventDisableTiming);
        inited = 1;
    }

    void *pS, *pG1, *pG2, *pG3, *pT, *pSC;
    void *pCNT, *pRP, *pCUR, *pEDGE, *pPPS, *pPPM, *pGC, *pWH, *pWL;
    cudaGetSymbolAddress(&pS,   d_S16);
    cudaGetSymbolAddress(&pG1,  d_G1);
    cudaGetSymbolAddress(&pG2,  d_G2);
    cudaGetSymbolAddress(&pG3,  d_G3);
    cudaGetSymbolAddress(&pT,   d_T);
    cudaGetSymbolAddress(&pSC,  d_SC);
    cudaGetSymbolAddress(&pCNT, d_CNT);
    cudaGetSymbolAddress(&pRP,  d_ROWPTR);
    cudaGetSymbolAddress(&pCUR, d_CUR);
    cudaGetSymbolAddress(&pEDGE, d_EDGE);
    cudaGetSymbolAddress(&pPPS, d_PPS);
    cudaGetSymbolAddress(&pPPM, d_PPM);
    cudaGetSymbolAddress(&pGC,  d_GCNT);
    cudaGetSymbolAddress(&pWH,  d_WH);
    cudaGetSymbolAddress(&pWL,  d_WL);

    __half* S  = (__half*)pS;
    __half* G1 = (__half*)pG1;
    __half* G2 = (__half*)pG2;
    __half* G3 = (__half*)pG3;
    float* T   = (float*)pT;
    float* SC  = (float*)pSC;
    int*   CNT = (int*)pCNT;
    int*   RP  = (int*)pRP;
    int*   CUR = (int*)pCUR;
    int2*  EDGE = (int2*)pEDGE;
    float* PPS = (float*)pPPS;
    float* PPM = (float*)pPPM;
    int*   GC  = (int*)pGC;
    uint32_t* WH = (uint32_t*)pWH;
    uint32_t* WL = (uint32_t*)pWL;

    const int gemm_grid = (N_NODES + 127) / 128;
    const int edge_grid = (N_EDGES + 255) / 256;
    const int warp_grid = (N_NODES * 32 + 255) / 256;

    // ---- fork: CSR build + W2/W3 prep on s2, concurrent with wprep(W1) + gemm1 ----
    cudaEventRecord(evFork, 0);
    cudaStreamWaitEvent(s2, evFork, 0);

    cudaMemsetAsync(CNT, 0, N_NODES * sizeof(int), s2);
    csr_count<<<edge_grid, 256, 0, s2>>>(dst, CNT);
    csr_scan<<<1, 1024, 0, s2>>>(CNT, RP, CUR);
    csr_fill<<<edge_grid, 256, 0, s2>>>(src, dst, ew, CUR, EDGE);
    cudaEventRecord(evCSR, s2);
    wprep<<<32, 256, 0, s2>>>(W2, WH + 8192,  WL + 8192);
    wprep<<<32, 256, 0, s2>>>(W3, WH + 16384, WL + 16384);
    cudaEventRecord(evW, s2);

    // ---- main: wprep(W1) + gemm1 ----
    wprep<<<32, 256>>>(W1, WH, WL);
    gemm_f16<float, true><<<gemm_grid, 256, GEMM_SMEM>>>(X, WH, WL, S, N_NODES);

    cudaStreamWaitEvent(0, evCSR, 0);
    gather_relu<<<warp_grid, 256>>>(RP, EDGE, S, b1, wa, G1, T, 0);

    cudaStreamWaitEvent(0, evW, 0);
    gemm_f16<__half, false><<<gemm_grid, 256, GEMM_SMEM>>>(G1, WH + 8192, WL + 8192, S, N_NODES);
    gather_relu<<<warp_grid, 256>>>(RP, EDGE, S, b2, wa + 128, G2, T, 1);
    gemm_f16<__half, false><<<gemm_grid, 256, GEMM_SMEM>>>(G2, WH + 16384, WL + 16384, S, N_NODES);
    gather_relu<<<warp_grid, 256>>>(RP, EDGE, S, b3, wa + 256, G3, T, 1);

    // ---- attention score ----
    gather_score<<<warp_grid, 256>>>(RP, EDGE, T, ba, SC);

    // ---- pooling + fused combine/FC ----
    pool_part<<<N_GRAPHS * 4, 384>>>(G1, G2, G3, SC, gi, PPS, PPM, GC);
    pool_final<<<N_GRAPHS, 384>>>(PPS, PPM, GC, Wf, bf, out);

    (void)in_sizes; (void)n_in; (void)out_size;
}